// round 3
// baseline (speedup 1.0000x reference)
#include <cuda_runtime.h>
#include <cuda_bf16.h>

// DeformableConvLayer: B=4, H=W=256, C=64, K=3x3, UNITS=1.
// Half-warp per pixel, float4 channel gathers, persistent grid-stride warps.
//   lanes 0..15  -> pixel 2q   (laneh = lane&15 covers channels 4*laneh..+3)
//   lanes 16..31 -> pixel 2q+1 (pairs never straddle a row or batch)
// Weights live in registers for the warp's lifetime (float4 x 9 per lane).
// Per pair: 9 warp-wide LDG.128 gathers serve both pixels; 4-step half-warp
// butterfly reduce; lanes 0 and 16 store adjacent outputs.

namespace {

constexpr int Hc = 256;
constexpr int Wc = 256;
constexpr int Cc = 64;
constexpr int PIX_TOTAL = 4 * Hc * Wc;              // 262144
constexpr int THREADS = 256;
constexpr int BLOCKS = 2048;
constexpr int TOTAL_WARPS = BLOCKS * (THREADS / 32);   // 16384
constexpr int PAIRS_TOTAL = PIX_TOTAL / 2;             // 131072
constexpr int PAIRS_PER_WARP = PAIRS_TOTAL / TOTAL_WARPS;  // 8

__global__ __launch_bounds__(THREADS)
void dcn_halfwarp(const float* __restrict__ input,    // [4,256,256,64]
                  const float* __restrict__ mask,     // [256,256]
                  const float* __restrict__ offset,   // [pix,18]
                  const float* __restrict__ kern,     // [9,64]
                  const float* __restrict__ bias,
                  float* __restrict__ out)            // [pix]
{
    const unsigned FULL = 0xffffffffu;
    const int lane   = threadIdx.x & 31;
    const int laneh  = lane & 15;          // lane within half-warp
    const int base16 = lane & 16;          // 0 or 16: my half's lane 0
    const int wid    = (blockIdx.x * THREADS + threadIdx.x) >> 5;

    // Weights once per warp: tap k, channels 4*laneh..4*laneh+3.
    float4 wk[9];
#pragma unroll
    for (int k = 0; k < 9; k++)
        wk[k] = *reinterpret_cast<const float4*>(kern + k * Cc + 4 * laneh);
    const float biasV = __ldg(bias);

    const int pair0 = wid * PAIRS_PER_WARP;

#pragma unroll 2
    for (int it = 0; it < PAIRS_PER_WARP; ++it) {
        const int pair = pair0 + it;
        const int pix  = pair * 2 + (base16 >> 4);   // my half's pixel
        const int b = pix >> 16;
        const int h = (pix >> 8) & 255;
        const int w = pix & 255;

        // ---- offsets: 18 floats per pixel, loaded by the owning half-warp ----
        const size_t obase = (size_t)pix * 18;
        const float offv0 = offset[obase + laneh];                       // j = 0..15
        const float offv1 = (laneh < 2) ? offset[obase + 16 + laneh] : 0.0f; // j = 16,17

        const int kk = (laneh < 9) ? laneh : 0;
        const float y_s = __shfl_sync(FULL, offv0, base16 + ((2 * kk) & 15));
        const float x_s = __shfl_sync(FULL, offv0, base16 + ((2 * kk + 1) & 15));
        const float y_8 = __shfl_sync(FULL, offv1, base16 + 0);
        const float x_8 = __shfl_sync(FULL, offv1, base16 + 1);
        const float y_off = (kk == 8) ? y_8 : y_s;
        const float x_off = (kk == 8) ? x_8 : x_s;

        // ---- tap coordinate (lanes with laneh<9 of each half) ----
        // Exact reference semantics: joint padded-grid zeroing, mask compare at
        // padded coords, offset gated by mask diff, floor+clip, padded sample.
        int packed = -1;
        if (laneh < 9) {
            const int ky = kk / 3;
            const int kx = kk - ky * 3;
            const int yb = h + ky - 1;
            const int xb = w + kx - 1;
            const bool inb = (yb >= 0) & (yb < Hc) & (xb >= 0) & (xb < Wc);
            const int yi = inb ? yb : 0;
            const int xi = inb ? xb : 0;

            const float p_mask = (yi >= 1 && xi >= 1)
                                     ? mask[(yi - 1) * Wc + (xi - 1)] : 0.0f;

            int yo = (int)floorf((float)yi + y_off);
            int xo = (int)floorf((float)xi + x_off);
            yo = min(max(yo, 0), Hc + 1);
            xo = min(max(xo, 0), Wc + 1);
            const float p_mask_off = (yo >= 1 && yo <= Hc && xo >= 1 && xo <= Wc)
                                         ? mask[(yo - 1) * Wc + (xo - 1)] : 0.0f;

            const float diff = (p_mask != p_mask_off) ? 1.0f : 0.0f;

            const float yf = fminf(fmaxf((float)yi + y_off * diff, 0.0f), 255.0f);
            const float xf = fminf(fmaxf((float)xi + x_off * diff, 0.0f), 255.0f);
            const int y0 = (int)floorf(yf);
            const int x0 = (int)floorf(xf);

            if (y0 >= 1 && x0 >= 1)          // padded sample: 0 when y0==0||x0==0
                packed = ((y0 - 1) << 8) | (x0 - 1);
        }

        const float* inp = input + (size_t)b * (Hc * Wc * Cc) + 4 * laneh;

        // ---- 9 gathers, one LDG.128 per tap serving both pixels ----
        float acc = 0.0f;
#pragma unroll
        for (int k = 0; k < 9; k++) {
            const int pk = __shfl_sync(FULL, packed, base16 + k);
            if (pk >= 0) {
                const float4 v = *reinterpret_cast<const float4*>(inp + pk * Cc);
                acc = fmaf(v.x, wk[k].x,
                      fmaf(v.y, wk[k].y,
                      fmaf(v.z, wk[k].z,
                      fmaf(v.w, wk[k].w, acc))));
            }
        }

        // ---- half-warp butterfly reduce (4 steps, shared by both pixels) ----
#pragma unroll
        for (int s = 8; s; s >>= 1)
            acc += __shfl_xor_sync(FULL, acc, s);

        if (laneh == 0)                      // lanes 0 & 16: adjacent addresses
            out[pix] = acc + biasV;
    }
}

} // namespace

extern "C" void kernel_launch(void* const* d_in, const int* in_sizes, int n_in,
                              void* d_out, int out_size)
{
    const float* input  = (const float*)d_in[0];
    const float* mask   = (const float*)d_in[1];
    const float* offset = (const float*)d_in[2];
    const float* kern   = (const float*)d_in[3];
    const float* bias   = (const float*)d_in[4];
    float* out = (float*)d_out;

    dcn_halfwarp<<<BLOCKS, THREADS>>>(input, mask, offset, kern, bias, out);
}

// round 4
// speedup vs baseline: 2.8617x; 2.8617x over previous
#include <cuda_runtime.h>
#include <cuda_bf16.h>

// DeformableConvLayer: B=4, H=W=256, C=64, K=3x3, UNITS=1.
// Two-phase algorithm:
//   Phase 1: P_k[pix] = <input[pix,:], kern[k,:]> for k=0..8  (dense, streaming)
//   Phase 2: out[pix] = bias + sum_k gather(P_k, deformed tap coords)
// The deformable gather moves from 9x256B vectors per pixel to 9x4B scalars.

namespace {

constexpr int Hc = 256;
constexpr int Wc = 256;
constexpr int Cc = 64;
constexpr int PIX = 4 * Hc * Wc;               // 262144

__device__ float g_P[9 * PIX];                 // 9.4 MB scratch (tap planes)

// ---------------- Phase 1: 9-way channel contraction ----------------
// Block = 128 threads = 128 consecutive pixels (half a row; never straddles rows).
// Input tile staged in smem with XOR-16 swizzle -> conflict-free LDS.128 reads.

constexpr int P1_T = 128;

__global__ __launch_bounds__(P1_T)
void dcn_phase1(const float* __restrict__ input,   // [PIX, 64]
                const float* __restrict__ kern)    // [9, 64]
{
    __shared__ float4 in_s[P1_T * 16];   // [pixel][c4 ^ (pixel&15)]
    __shared__ float4 w_s[9 * 16];       // [k][c4]

    const int t = threadIdx.x;
    const int pixbase = blockIdx.x * P1_T;

    // weights -> smem (144 float4)
    for (int i = t; i < 9 * 16; i += P1_T)
        w_s[i] = reinterpret_cast<const float4*>(kern)[i];

    // input tile -> smem, coalesced global reads, swizzled smem writes
    const float4* in4 = reinterpret_cast<const float4*>(input) + (size_t)pixbase * 16;
#pragma unroll
    for (int i = 0; i < 16; i++) {
        const int g  = i * P1_T + t;
        const int p  = g >> 4;
        const int c4 = g & 15;
        in_s[p * 16 + (c4 ^ (p & 15))] = in4[g];
    }
    __syncthreads();

    float acc[9];
#pragma unroll
    for (int k = 0; k < 9; k++) acc[k] = 0.0f;

#pragma unroll
    for (int c4 = 0; c4 < 16; c4++) {
        const float4 v = in_s[t * 16 + (c4 ^ (t & 15))];   // conflict-free
#pragma unroll
        for (int k = 0; k < 9; k++) {
            const float4 wv = w_s[k * 16 + c4];            // broadcast
            acc[k] = fmaf(v.x, wv.x,
                     fmaf(v.y, wv.y,
                     fmaf(v.z, wv.z,
                     fmaf(v.w, wv.w, acc[k]))));
        }
    }

    // coalesced plane stores
#pragma unroll
    for (int k = 0; k < 9; k++)
        g_P[k * PIX + pixbase + t] = acc[k];
}

// ---------------- Phase 2: deformable scalar gather ----------------
// Block = 256 threads = one image row (b, h fixed). Offsets staged coalesced.

constexpr int P2_T = 256;

__global__ __launch_bounds__(P2_T)
void dcn_phase2(const float* __restrict__ mask,     // [256,256]
                const float* __restrict__ offset,   // [PIX,18]
                const float* __restrict__ bias,
                float* __restrict__ out)            // [PIX]
{
    __shared__ float soff[P2_T * 18];    // 18 KB
    __shared__ float smask[3 * 256];     // rows h-2..h

    const int t = threadIdx.x;
    const int pixbase = blockIdx.x * P2_T;
    const int b = pixbase >> 16;
    const int h = (pixbase >> 8) & 255;
    const int w = t;

    // stage offsets: 256*18 floats = 1152 float4, coalesced
    {
        const float4* off4 = reinterpret_cast<const float4*>(offset + (size_t)pixbase * 18);
        float4* soff4 = reinterpret_cast<float4*>(soff);
#pragma unroll
        for (int i = 0; i < 4; i++)
            soff4[i * P2_T + t] = off4[i * P2_T + t];
        if (t < 1152 - 4 * P2_T)
            soff4[4 * P2_T + t] = off4[4 * P2_T + t];
    }
    // stage base-mask rows h-2 .. h
#pragma unroll
    for (int r = 0; r < 3; r++) {
        const int row = h - 2 + r;
        smask[r * 256 + t] = (row >= 0) ? mask[row * Wc + t] : 0.0f;
    }
    __syncthreads();

    float acc = __ldg(bias);

#pragma unroll
    for (int k = 0; k < 9; k++) {
        const int ky = k / 3;
        const int kx = k - ky * 3;
        const int yb = h + ky - 1;
        const int xb = w + kx - 1;
        // joint padded-index-grid zeroing (reference semantics)
        const bool inb = (yb >= 0) & (yb < Hc) & (xb >= 0) & (xb < Wc);
        const int yi = inb ? yb : 0;
        const int xi = inb ? xb : 0;

        const float2 off2 = *reinterpret_cast<const float2*>(&soff[t * 18 + 2 * k]);
        const float y_off = off2.x;
        const float x_off = off2.y;

        // mask at base tap (padded coords; pad ring = 0)
        float p_mask = 0.0f;
        if (inb & (yb >= 1) & (xb >= 1))
            p_mask = smask[ky * 256 + (w + kx - 2)];

        // mask at offset point: floor, clip to padded range [0,257]
        int yo = (int)floorf((float)yi + y_off);
        int xo = (int)floorf((float)xi + x_off);
        yo = min(max(yo, 0), Hc + 1);
        xo = min(max(xo, 0), Wc + 1);
        float p_mask_off = 0.0f;
        if (yo >= 1 && yo <= Hc && xo >= 1 && xo <= Wc)
            p_mask_off = __ldg(&mask[(yo - 1) * Wc + (xo - 1)]);

        const float diff = (p_mask != p_mask_off) ? 1.0f : 0.0f;

        const float yf = fminf(fmaxf((float)yi + y_off * diff, 0.0f), 255.0f);
        const float xf = fminf(fmaxf((float)xi + x_off * diff, 0.0f), 255.0f);
        const int y0 = (int)floorf(yf);
        const int x0 = (int)floorf(xf);

        // padded-input sample: zero when y0==0 || x0==0, else plane value at (y0-1,x0-1)
        if (y0 >= 1 && x0 >= 1)
            acc += g_P[k * PIX + b * (Hc * Wc) + (y0 - 1) * Wc + (x0 - 1)];
    }

    out[pixbase + t] = acc;
}

} // namespace

extern "C" void kernel_launch(void* const* d_in, const int* in_sizes, int n_in,
                              void* d_out, int out_size)
{
    const float* input  = (const float*)d_in[0];   // [4,256,256,64]
    const float* mask   = (const float*)d_in[1];   // [1,256,256,1]
    const float* offset = (const float*)d_in[2];   // [4,256,256,18]
    const float* kern   = (const float*)d_in[3];   // [3,3,64,1]
    const float* bias   = (const float*)d_in[4];   // [1]
    float* out = (float*)d_out;

    dcn_phase1<<<PIX / P1_T, P1_T>>>(input, kern);
    dcn_phase2<<<PIX / P2_T, P2_T>>>(mask, offset, bias, out);
}